// round 10
// baseline (speedup 1.0000x reference)
#include <cuda_runtime.h>
#include <cstdint>

// Problem constants
#define NN 4096
#define FF 128
#define HID 128
#define HEADS 8
#define HDIM 16
#define CC 64
#define EE 131072

#define GRID 148      // 1 block/SM -> guaranteed co-resident (GB300 has 152 SMs)
#define NT 256

// ---------------- scratch (no allocation allowed) ----------------
__device__ float g_H[NN * HID];
__device__ float g_G[NN * HID];
__device__ float g_G2[NN * HID];
__device__ float g_QKV[NN * 3 * FF];
__device__ float g_O[NN * FF];
__device__ float g_GNN[NN * CC];
__device__ float g_Wp[FF * CC];
__device__ float g_bp[CC];
__device__ float g_dinv[NN];
__device__ int   g_count[NN];          // invariant: all-zero at kernel entry
__device__ int   g_off[NN + 1];
__device__ int   g_cur[NN];
__device__ int   g_srow[EE];

// barrier + ticket state (zero-initialized; invariants restored every launch)
__device__ int             g_ticket[8];
__device__ int             g_bar_cnt;
__device__ volatile unsigned g_bar_gen;

// ---------------- grid barrier (sense-reversal) ----------------
__device__ __forceinline__ void grid_barrier(int reset_phase) {
    __threadfence();
    __syncthreads();
    if (threadIdx.x == 0) {
        unsigned gen = g_bar_gen;
        if (atomicAdd(&g_bar_cnt, 1) == GRID - 1) {
            g_bar_cnt = 0;
            g_ticket[reset_phase] = 0;     // phase just completed; safe to reset
            __threadfence();
            g_bar_gen = gen + 1;
        } else {
            while (g_bar_gen == gen) __nanosleep(64);
        }
    }
    __syncthreads();
    __threadfence();
}

// ---------------- ticket-queue phase runner ----------------
template <typename F>
__device__ __forceinline__ void run_phase(int p, int ntasks, F&& f) {
    __shared__ int s_task;
    while (true) {
        __syncthreads();                    // protect smem reuse across tasks
        if (threadIdx.x == 0) s_task = atomicAdd(&g_ticket[p], 1);
        __syncthreads();
        int t = s_task;
        if (t >= ntasks) break;
        f(t);
    }
}

// ---------------- task bodies ----------------

// Wp[i][c] = sum_o out_w[o][i]*proj_w[o][c];  bp[c] = proj_b[c] + sum_o out_b[o]*proj_w[o][c]
__device__ void wp_task(const float* out_w, const float* out_b,
                        const float* proj_w, const float* proj_b, int task) {
    int gid = task * NT + threadIdx.x;    // 32 tasks -> 8192 threads
    int i = gid >> 6;
    int c = gid & 63;
    float acc = 0.0f;
    #pragma unroll 8
    for (int o = 0; o < FF; o++)
        acc += out_w[o * FF + i] * proj_w[o * CC + c];
    g_Wp[i * CC + c] = acc;
    if (i == 0) {
        float b = proj_b[c];
        #pragma unroll 8
        for (int o = 0; o < FF; o++)
            b += out_b[o] * proj_w[o * CC + c];
        g_bp[c] = b;
    }
}

// histogram: 128 tasks x 1024 edges (int4 loads)
__device__ void hist_task(const int* col, int task) {
    const int4* c4 = (const int4*)col;
    int4 v = c4[task * NT + threadIdx.x];
    atomicAdd(&g_count[v.x], 1);
    atomicAdd(&g_count[v.y], 1);
    atomicAdd(&g_count[v.z], 1);
    atomicAdd(&g_count[v.w], 1);
}

// exclusive scan of g_count[4096] with 256 threads; writes off/cur/dinv, re-zeroes cnt
__device__ void scan_task(char* smraw) {
    int* wsum = (int*)smraw;     // 8 ints
    int tid = threadIdx.x;
    int lane = tid & 31, warp = tid >> 5;
    int base = tid * 16;
    int v[16];
    int s = 0;
    #pragma unroll
    for (int i = 0; i < 16; i++) { v[i] = g_count[base + i]; s += v[i]; }
    int x = s;
    #pragma unroll
    for (int d = 1; d < 32; d <<= 1) {
        int y = __shfl_up_sync(0xffffffffu, x, d);
        if (lane >= d) x += y;
    }
    if (lane == 31) wsum[warp] = x;
    __syncthreads();
    if (warp == 0 && lane < 8) {
        int w = wsum[lane];
        #pragma unroll
        for (int d = 1; d < 8; d <<= 1) {
            int y = __shfl_up_sync(0x000000ffu, w, d);
            if (lane >= d) w += y;
        }
        wsum[lane] = w;
    }
    __syncthreads();
    int run = x - s + (warp ? wsum[warp - 1] : 0);
    #pragma unroll
    for (int i = 0; i < 16; i++) {
        g_off[base + i] = run;
        g_cur[base + i] = run;
        g_dinv[base + i] = rsqrtf(1.0f + (float)v[i]);
        g_count[base + i] = 0;            // restore invariant for next launch
        run += v[i];
    }
    if (tid == 255) g_off[NN] = run;
}

// reorder: 64 tasks x 2048 edges
__device__ void reorder_task(const int* row, const int* col, int task) {
    int base = task * 2048 + threadIdx.x;
    #pragma unroll
    for (int i = 0; i < 8; i++) {
        int e = base + i * 256;
        int pos = atomicAdd(&g_cur[col[e]], 1);
        g_srow[pos] = row[e];
    }
}

// gather: task = 8 destination nodes, warp per node
__device__ void gather_task(const float* H, const float* bias, float* out, int task) {
    int warp = threadIdx.x >> 5;
    int lane = threadIdx.x & 31;
    int c = task * 8 + warp;
    int d = lane * 4;

    float dc = g_dinv[c];
    float4 hs = *(const float4*)(H + c * HID + d);
    float4 acc = make_float4(dc * hs.x, dc * hs.y, dc * hs.z, dc * hs.w);

    int i = g_off[c];
    int e_ = g_off[c + 1];
    for (; i + 4 <= e_; i += 4) {
        int r0 = g_srow[i], r1 = g_srow[i + 1], r2 = g_srow[i + 2], r3 = g_srow[i + 3];
        float w0 = g_dinv[r0], w1 = g_dinv[r1], w2 = g_dinv[r2], w3 = g_dinv[r3];
        float4 h0 = *(const float4*)(H + r0 * HID + d);
        float4 h1 = *(const float4*)(H + r1 * HID + d);
        float4 h2 = *(const float4*)(H + r2 * HID + d);
        float4 h3 = *(const float4*)(H + r3 * HID + d);
        acc.x += w0 * h0.x + w1 * h1.x + w2 * h2.x + w3 * h3.x;
        acc.y += w0 * h0.y + w1 * h1.y + w2 * h2.y + w3 * h3.y;
        acc.z += w0 * h0.z + w1 * h1.z + w2 * h2.z + w3 * h3.z;
        acc.w += w0 * h0.w + w1 * h1.w + w2 * h2.w + w3 * h3.w;
    }
    for (; i < e_; i++) {
        int r = g_srow[i];
        float w = g_dinv[r];
        float4 h = *(const float4*)(H + r * HID + d);
        acc.x += w * h.x; acc.y += w * h.y; acc.z += w * h.z; acc.w += w * h.w;
    }

    float4 b = *(const float4*)(bias + d);
    float4 v;
    v.x = fmaxf(b.x + dc * acc.x, 0.0f);
    v.y = fmaxf(b.y + dc * acc.y, 0.0f);
    v.z = fmaxf(b.z + dc * acc.z, 0.0f);
    v.w = fmaxf(b.w + dc * acc.w, 0.0f);
    *(float4*)(out + c * HID + d) = v;
}

// ---------------- software-pipelined SGEMM task ----------------
template <int BM, int BN, bool TRANSB, bool HAS_BIAS, bool DO_ADD, bool DO_RELU>
__device__ void pgemm_task(char* smraw,
                           const float* A, const float* B,
                           const float* bias, const float* add, float* C,
                           int M, int N, int K, int bx, int by) {
    constexpr int NA = BM / 32;
    constexpr int NB = BN / 32;
    constexpr int RM = BM / 16;
    constexpr int RN = BN / 16;
    typedef float AsRow[32][BM + 4];
    typedef float BsRow[32][BN];
    AsRow* As = reinterpret_cast<AsRow*>(smraw);
    BsRow* Bs = reinterpret_cast<BsRow*>(smraw + 2 * 32 * (BM + 4) * sizeof(float));

    const int tid = threadIdx.x;
    const int tx = tid & 15, ty = tid >> 4;
    const int m0 = by * BM, n0 = bx * BN;

    float4 pa[NA], pb[NB];

    auto loadA = [&](int k0) {
        #pragma unroll
        for (int i = 0; i < NA; i++) {
            int fl = tid + i * 256;
            int ar = fl >> 3, ac = (fl & 7) * 4;
            pa[i] = *(const float4*)(A + (m0 + ar) * K + k0 + ac);
        }
    };
    auto storeA = [&](int buf) {
        #pragma unroll
        for (int i = 0; i < NA; i++) {
            int fl = tid + i * 256;
            int ar = fl >> 3, ac = (fl & 7) * 4;
            As[buf][ac + 0][ar] = pa[i].x;
            As[buf][ac + 1][ar] = pa[i].y;
            As[buf][ac + 2][ar] = pa[i].z;
            As[buf][ac + 3][ar] = pa[i].w;
        }
    };
    auto loadB = [&](int k0) {
        #pragma unroll
        for (int i = 0; i < NB; i++) {
            int fl = tid + i * 256;
            if (!TRANSB) {
                int br = fl / (BN / 4), bc = (fl % (BN / 4)) * 4;
                pb[i] = *(const float4*)(B + (k0 + br) * N + n0 + bc);
            } else {
                int bn = fl >> 3, bk = (fl & 7) * 4;
                pb[i] = *(const float4*)(B + (n0 + bn) * K + k0 + bk);
            }
        }
    };
    auto storeB = [&](int buf) {
        #pragma unroll
        for (int i = 0; i < NB; i++) {
            int fl = tid + i * 256;
            if (!TRANSB) {
                int br = fl / (BN / 4), bc = (fl % (BN / 4)) * 4;
                *(float4*)&Bs[buf][br][bc] = pb[i];
            } else {
                int bn = fl >> 3, bk = (fl & 7) * 4;
                Bs[buf][bk + 0][bn] = pb[i].x;
                Bs[buf][bk + 1][bn] = pb[i].y;
                Bs[buf][bk + 2][bn] = pb[i].z;
                Bs[buf][bk + 3][bn] = pb[i].w;
            }
        }
    };

    loadA(0); loadB(0);
    storeA(0); storeB(0);
    __syncthreads();

    float acc[RM][RN];
    #pragma unroll
    for (int i = 0; i < RM; i++)
        #pragma unroll
        for (int j = 0; j < RN; j++) acc[i][j] = 0.0f;

    const int nit = K >> 5;
    for (int it = 0; it < nit; it++) {
        const int cur = it & 1;
        if (it + 1 < nit) { loadA((it + 1) * 32); loadB((it + 1) * 32); }

        #pragma unroll
        for (int kk = 0; kk < 32; kk++) {
            float a[RM], b[RN];
            if (RM == 4) {
                float4 av = *(const float4*)&As[cur][kk][ty * 4];
                a[0] = av.x; a[1] = av.y; a[2] = av.z; a[3] = av.w;
            } else {
                float2 av = *(const float2*)&As[cur][kk][ty * 2];
                a[0] = av.x; a[1] = av.y;
            }
            if (RN == 4) {
                float4 bv = *(const float4*)&Bs[cur][kk][tx * 4];
                b[0] = bv.x; b[1] = bv.y; b[2] = bv.z; b[3] = bv.w;
            } else {
                float2 bv = *(const float2*)&Bs[cur][kk][tx * 2];
                b[0] = bv.x; b[1] = bv.y;
            }
            #pragma unroll
            for (int i = 0; i < RM; i++)
                #pragma unroll
                for (int j = 0; j < RN; j++)
                    acc[i][j] += a[i] * b[j];
        }

        if (it + 1 < nit) {
            storeA((it + 1) & 1); storeB((it + 1) & 1);
            __syncthreads();
        }
    }

    #pragma unroll
    for (int i = 0; i < RM; i++) {
        int r = m0 + ty * RM + i;
        #pragma unroll
        for (int j = 0; j < RN; j++) {
            int c = n0 + tx * RN + j;
            float v = acc[i][j];
            if (HAS_BIAS) v += bias[c];
            if (DO_ADD)  v += add[r * N + c];
            if (DO_RELU) v = fmaxf(v, 0.0f);
            C[r * N + c] = v;
        }
    }
}

// ---------------- tensor-core flash attention task ----------------
__device__ __forceinline__ unsigned cvt_tf32(float f) {
    unsigned u; asm("cvt.rna.tf32.f32 %0, %1;" : "=r"(u) : "f"(f)); return u;
}
__device__ __forceinline__ unsigned f16x2_hl(float hi, float lo) {
    unsigned u; asm("cvt.rn.f16x2.f32 %0, %1, %2;" : "=r"(u) : "f"(hi), "f"(lo)); return u;
}
__device__ __forceinline__ float ex2(float x) {
    float y; asm("ex2.approx.ftz.f32 %0, %1;" : "=f"(y) : "f"(x)); return y;
}
__device__ __forceinline__ void mma_tf32(float c[4], const unsigned a[4],
                                         unsigned b0, unsigned b1) {
    asm("mma.sync.aligned.m16n8k8.row.col.f32.tf32.tf32.f32 "
        "{%0,%1,%2,%3}, {%4,%5,%6,%7}, {%8,%9}, {%0,%1,%2,%3};"
        : "+f"(c[0]), "+f"(c[1]), "+f"(c[2]), "+f"(c[3])
        : "r"(a[0]), "r"(a[1]), "r"(a[2]), "r"(a[3]), "r"(b0), "r"(b1));
}
__device__ __forceinline__ void mma_f16(float c[4], unsigned a0, unsigned a1,
                                        unsigned a2, unsigned a3,
                                        unsigned b0, unsigned b1) {
    asm("mma.sync.aligned.m16n8k16.row.col.f32.f16.f16.f32 "
        "{%0,%1,%2,%3}, {%4,%5,%6,%7}, {%8,%9}, {%0,%1,%2,%3};"
        : "+f"(c[0]), "+f"(c[1]), "+f"(c[2]), "+f"(c[3])
        : "r"(a0), "r"(a1), "r"(a2), "r"(a3), "r"(b0), "r"(b1));
}

__device__ void attn_task(char* smraw, const float* QKV, float* O, int task) {
    unsigned (*Ks)[17] = reinterpret_cast<unsigned(*)[17]>(smraw);
    float    (*Vs)[17] = reinterpret_cast<float(*)[17]>(smraw + 64 * 17 * 4);

    const int h    = task >> 5;
    const int qt   = task & 31;
    const int warp = threadIdx.x >> 5;
    const int lane = threadIdx.x & 31;
    const int g    = lane >> 2;
    const int t    = lane & 3;
    const int q0   = qt * 128 + warp * 16;

    const float qscale = 0.25f * 1.4426950408889634f;

    unsigned qa[2][4];
    {
        const float* Qb = QKV + h * HDIM;
        #pragma unroll
        for (int kk = 0; kk < 2; kk++) {
            qa[kk][0] = cvt_tf32(Qb[(q0 + g)     * 384 + kk * 8 + t]     * qscale);
            qa[kk][1] = cvt_tf32(Qb[(q0 + g + 8) * 384 + kk * 8 + t]     * qscale);
            qa[kk][2] = cvt_tf32(Qb[(q0 + g)     * 384 + kk * 8 + t + 4] * qscale);
            qa[kk][3] = cvt_tf32(Qb[(q0 + g + 8) * 384 + kk * 8 + t + 4] * qscale);
        }
    }

    float o[2][4];
    #pragma unroll
    for (int dt = 0; dt < 2; dt++)
        #pragma unroll
        for (int i = 0; i < 4; i++) o[dt][i] = 0.0f;
    float l0 = 0.0f, l1 = 0.0f;

    for (int k0 = 0; k0 < NN; k0 += 64) {
        __syncthreads();
        {
            int key = threadIdx.x & 63;
            int dh  = (threadIdx.x >> 6) * 4;
            const float* kb = QKV + (k0 + key) * 384 + FF + h * HDIM + dh;
            float4 kv = *(const float4*)kb;
            float4 vv = *(const float4*)(kb + FF);
            Ks[key][dh + 0] = cvt_tf32(kv.x);
            Ks[key][dh + 1] = cvt_tf32(kv.y);
            Ks[key][dh + 2] = cvt_tf32(kv.z);
            Ks[key][dh + 3] = cvt_tf32(kv.w);
            Vs[key][dh + 0] = vv.x;
            Vs[key][dh + 1] = vv.y;
            Vs[key][dh + 2] = vv.z;
            Vs[key][dh + 3] = vv.w;
        }
        __syncthreads();

        float c[8][4];
        #pragma unroll
        for (int j = 0; j < 8; j++) {
            c[j][0] = c[j][1] = c[j][2] = c[j][3] = 0.0f;
            #pragma unroll
            for (int kk = 0; kk < 2; kk++) {
                unsigned b0 = Ks[j * 8 + g][kk * 8 + t];
                unsigned b1 = Ks[j * 8 + g][kk * 8 + t + 4];
                mma_tf32(c[j], qa[kk], b0, b1);
            }
        }

        #pragma unroll
        for (int j = 0; j < 8; j++) {
            c[j][0] = ex2(c[j][0] - 8.0f);
            c[j][1] = ex2(c[j][1] - 8.0f);
            c[j][2] = ex2(c[j][2] - 8.0f);
            c[j][3] = ex2(c[j][3] - 8.0f);
            l0 += c[j][0] + c[j][1];
            l1 += c[j][2] + c[j][3];
        }

        #pragma unroll
        for (int kt = 0; kt < 4; kt++) {
            unsigned a0 = f16x2_hl(c[2 * kt][1],     c[2 * kt][0]);
            unsigned a1 = f16x2_hl(c[2 * kt][3],     c[2 * kt][2]);
            unsigned a2 = f16x2_hl(c[2 * kt + 1][1], c[2 * kt + 1][0]);
            unsigned a3 = f16x2_hl(c[2 * kt + 1][3], c[2 * kt + 1][2]);
            int kb = kt * 16;
            #pragma unroll
            for (int dt = 0; dt < 2; dt++) {
                int d = dt * 8 + g;
                unsigned b0 = f16x2_hl(Vs[kb + 2 * t + 1][d], Vs[kb + 2 * t][d]);
                unsigned b1 = f16x2_hl(Vs[kb + 2 * t + 9][d], Vs[kb + 2 * t + 8][d]);
                mma_f16(o[dt], a0, a1, a2, a3, b0, b1);
            }
        }
    }

    l0 += __shfl_xor_sync(0xffffffffu, l0, 1);
    l0 += __shfl_xor_sync(0xffffffffu, l0, 2);
    l1 += __shfl_xor_sync(0xffffffffu, l1, 1);
    l1 += __shfl_xor_sync(0xffffffffu, l1, 2);
    float inv0 = 1.0f / l0;
    float inv1 = 1.0f / l1;

    #pragma unroll
    for (int dt = 0; dt < 2; dt++) {
        int col = h * HDIM + dt * 8 + 2 * t;
        float2 v0 = make_float2(o[dt][0] * inv0, o[dt][1] * inv0);
        float2 v1 = make_float2(o[dt][2] * inv1, o[dt][3] * inv1);
        *(float2*)(O + (q0 + g)     * FF + col) = v0;
        *(float2*)(O + (q0 + g + 8) * FF + col) = v1;
    }
}

// ---------------- the megakernel ----------------
__global__ __launch_bounds__(NT)
void mega_kernel(const float* __restrict__ x, const int* __restrict__ edge_index,
                 const float* __restrict__ W1, const float* __restrict__ b1,
                 const float* __restrict__ W2, const float* __restrict__ b2,
                 const float* __restrict__ W3, const float* __restrict__ b3,
                 const float* __restrict__ in_w, const float* __restrict__ in_b,
                 const float* __restrict__ out_w, const float* __restrict__ out_b,
                 const float* __restrict__ proj_w, const float* __restrict__ proj_b,
                 float* __restrict__ out) {
    // max smem user: pgemm<64,64>: 2*32*68*4 + 2*32*64*4 = 17408 + 16384 = 33792 B
    __shared__ __align__(16) char smraw[33792];

    const int* row = edge_index;
    const int* col = edge_index + EE;

    // P0: Wp precompute (32) + degree histogram (128)
    run_phase(0, 32 + 128, [&](int t) {
        if (t < 32) wp_task(out_w, out_b, proj_w, proj_b, t);
        else        hist_task(col, t - 32);
    });
    grid_barrier(0);

    // P1: scan (1) + QKV GEMM (384) + conv1 GEMM (256)
    run_phase(1, 1 + 384 + 256, [&](int t) {
        if (t == 0)       scan_task(smraw);
        else if (t <= 384) {
            int tt = t - 1;
            pgemm_task<64, 64, true, true, false, false>(
                smraw, x, in_w, in_b, nullptr, g_QKV, NN, 3 * FF, FF, tt % 6, tt / 6);
        } else {
            int tt = t - 385;
            pgemm_task<64, 32, false, false, false, false>(
                smraw, x, W1, nullptr, nullptr, g_H, NN, HID, FF, tt % 4, tt / 4);
        }
    });
    grid_barrier(1);

    // P2: attention (256) + reorder (64)
    run_phase(2, 256 + 64, [&](int t) {
        if (t < 256) attn_task(smraw, g_QKV, g_O, t);
        else         reorder_task(row, col, t - 256);
    });
    grid_barrier(2);

    // P3: gather1 (512)
    run_phase(3, 512, [&](int t) { gather_task(g_H, b1, g_G, t); });
    grid_barrier(3);

    // P4: conv2 GEMM (256)
    run_phase(4, 256, [&](int t) {
        pgemm_task<64, 32, false, false, false, false>(
            smraw, g_G, W2, nullptr, nullptr, g_H, NN, HID, HID, t % 4, t / 4);
    });
    grid_barrier(4);

    // P5: gather2 (512)
    run_phase(5, 512, [&](int t) { gather_task(g_H, b2, g_G2, t); });
    grid_barrier(5);

    // P6: GNN head GEMM (256)
    run_phase(6, 256, [&](int t) {
        pgemm_task<32, 32, false, true, false, false>(
            smraw, g_G2, W3, b3, nullptr, g_GNN, NN, CC, HID, t % 2, t / 2);
    });
    grid_barrier(6);

    // P7: final fused GEMM: out = relu(O @ Wp + bp + GNN)
    run_phase(7, 256, [&](int t) {
        pgemm_task<32, 32, false, true, true, true>(
            smraw, g_O, g_Wp, g_bp, g_GNN, out, NN, CC, FF, t % 2, t / 2);
    });
    grid_barrier(7);   // also resets ticket[7] for the next launch
}

// ---------------- launch ----------------
extern "C" void kernel_launch(void* const* d_in, const int* in_sizes, int n_in,
                              void* d_out, int out_size) {
    const float* x          = (const float*)d_in[0];
    const int*   edge_index = (const int*)  d_in[1];
    const float* W1         = (const float*)d_in[2];
    const float* b1         = (const float*)d_in[3];
    const float* W2         = (const float*)d_in[4];
    const float* b2         = (const float*)d_in[5];
    const float* W3         = (const float*)d_in[6];
    const float* b3         = (const float*)d_in[7];
    const float* in_w       = (const float*)d_in[8];
    const float* in_b       = (const float*)d_in[9];
    const float* out_w      = (const float*)d_in[10];
    const float* out_b      = (const float*)d_in[11];
    const float* proj_w     = (const float*)d_in[12];
    const float* proj_b     = (const float*)d_in[13];
    float* out = (float*)d_out;

    mega_kernel<<<GRID, NT>>>(x, edge_index, W1, b1, W2, b2, W3, b3,
                              in_w, in_b, out_w, out_b, proj_w, proj_b, out);
}

// round 12
// speedup vs baseline: 1.2777x; 1.2777x over previous
#include <cuda_runtime.h>
#include <cstdint>

// Problem constants
#define NN 4096
#define FF 128
#define HID 128
#define HEADS 8
#define HDIM 16
#define CC 64
#define EE 131072

#define GRID 296      // 2 blocks/SM on 148 SMs; capacity >= 3/SM so co-residency is guaranteed
#define NT 256

// ---------------- scratch (no allocation allowed) ----------------
__device__ float g_H[NN * HID];
__device__ float g_G[NN * HID];
__device__ float g_G2[NN * HID];
__device__ float g_QKV[NN * 3 * FF];
__device__ float g_O[NN * FF];
__device__ float g_GNN[NN * CC];
__device__ float g_Wp[FF * CC];
__device__ float g_bp[CC];
__device__ float g_dinv[NN];
__device__ int   g_count[NN];          // invariant: all-zero at kernel entry
__device__ int   g_off[NN + 1];
__device__ int   g_cur[NN];
__device__ int   g_srow[EE];

// barrier + ticket state (zero-initialized; invariants restored every launch)
__device__ int             g_ticket[8];
__device__ int             g_bar_cnt;
__device__ volatile unsigned g_bar_gen;

// ---------------- grid barrier (sense-reversal) ----------------
__device__ __forceinline__ void grid_barrier(int reset_phase) {
    __threadfence();
    __syncthreads();
    if (threadIdx.x == 0) {
        unsigned gen = g_bar_gen;
        if (atomicAdd(&g_bar_cnt, 1) == GRID - 1) {
            g_bar_cnt = 0;
            g_ticket[reset_phase] = 0;     // phase just completed; safe to reset
            __threadfence();
            g_bar_gen = gen + 1;
        } else {
            while (g_bar_gen == gen) __nanosleep(64);
        }
    }
    __syncthreads();
    __threadfence();
}

// ---------------- ticket-queue phase runner ----------------
template <typename F>
__device__ __forceinline__ void run_phase(int p, int ntasks, F&& f) {
    __shared__ int s_task;
    while (true) {
        __syncthreads();                    // protect smem reuse across tasks
        if (threadIdx.x == 0) s_task = atomicAdd(&g_ticket[p], 1);
        __syncthreads();
        int t = s_task;
        if (t >= ntasks) break;
        f(t);
    }
}

// ---------------- task bodies ----------------

// Wp[i][c] = sum_o out_w[o][i]*proj_w[o][c];  bp[c] = proj_b[c] + sum_o out_b[o]*proj_w[o][c]
__device__ void wp_task(const float* out_w, const float* out_b,
                        const float* proj_w, const float* proj_b, int task) {
    int gid = task * NT + threadIdx.x;    // 32 tasks -> 8192 threads
    int i = gid >> 6;
    int c = gid & 63;
    float acc = 0.0f;
    #pragma unroll 8
    for (int o = 0; o < FF; o++)
        acc += out_w[o * FF + i] * proj_w[o * CC + c];
    g_Wp[i * CC + c] = acc;
    if (i == 0) {
        float b = proj_b[c];
        #pragma unroll 8
        for (int o = 0; o < FF; o++)
            b += out_b[o] * proj_w[o * CC + c];
        g_bp[c] = b;
    }
}

// histogram: 128 tasks x 1024 edges (int4 loads)
__device__ void hist_task(const int* col, int task) {
    const int4* c4 = (const int4*)col;
    int4 v = c4[task * NT + threadIdx.x];
    atomicAdd(&g_count[v.x], 1);
    atomicAdd(&g_count[v.y], 1);
    atomicAdd(&g_count[v.z], 1);
    atomicAdd(&g_count[v.w], 1);
}

// exclusive scan of g_count[4096] with 256 threads; writes off/cur/dinv, re-zeroes cnt
__device__ void scan_task(char* smraw) {
    int* wsum = (int*)smraw;     // 8 ints
    int tid = threadIdx.x;
    int lane = tid & 31, warp = tid >> 5;
    int base = tid * 16;
    int v[16];
    int s = 0;
    #pragma unroll
    for (int i = 0; i < 16; i++) { v[i] = g_count[base + i]; s += v[i]; }
    int x = s;
    #pragma unroll
    for (int d = 1; d < 32; d <<= 1) {
        int y = __shfl_up_sync(0xffffffffu, x, d);
        if (lane >= d) x += y;
    }
    if (lane == 31) wsum[warp] = x;
    __syncthreads();
    if (warp == 0 && lane < 8) {
        int w = wsum[lane];
        #pragma unroll
        for (int d = 1; d < 8; d <<= 1) {
            int y = __shfl_up_sync(0x000000ffu, w, d);
            if (lane >= d) w += y;
        }
        wsum[lane] = w;
    }
    __syncthreads();
    int run = x - s + (warp ? wsum[warp - 1] : 0);
    #pragma unroll
    for (int i = 0; i < 16; i++) {
        g_off[base + i] = run;
        g_cur[base + i] = run;
        g_dinv[base + i] = rsqrtf(1.0f + (float)v[i]);
        g_count[base + i] = 0;            // restore invariant for next launch
        run += v[i];
    }
    if (tid == 255) g_off[NN] = run;
}

// reorder: 64 tasks x 2048 edges
__device__ void reorder_task(const int* row, const int* col, int task) {
    int base = task * 2048 + threadIdx.x;
    #pragma unroll
    for (int i = 0; i < 8; i++) {
        int e = base + i * 256;
        int pos = atomicAdd(&g_cur[col[e]], 1);
        g_srow[pos] = row[e];
    }
}

// gather: task = 8 destination nodes, warp per node
__device__ void gather_task(const float* H, const float* bias, float* out, int task) {
    int warp = threadIdx.x >> 5;
    int lane = threadIdx.x & 31;
    int c = task * 8 + warp;
    int d = lane * 4;

    float dc = g_dinv[c];
    float4 hs = *(const float4*)(H + c * HID + d);
    float4 acc = make_float4(dc * hs.x, dc * hs.y, dc * hs.z, dc * hs.w);

    int i = g_off[c];
    int e_ = g_off[c + 1];
    for (; i + 4 <= e_; i += 4) {
        int r0 = g_srow[i], r1 = g_srow[i + 1], r2 = g_srow[i + 2], r3 = g_srow[i + 3];
        float w0 = g_dinv[r0], w1 = g_dinv[r1], w2 = g_dinv[r2], w3 = g_dinv[r3];
        float4 h0 = *(const float4*)(H + r0 * HID + d);
        float4 h1 = *(const float4*)(H + r1 * HID + d);
        float4 h2 = *(const float4*)(H + r2 * HID + d);
        float4 h3 = *(const float4*)(H + r3 * HID + d);
        acc.x += w0 * h0.x + w1 * h1.x + w2 * h2.x + w3 * h3.x;
        acc.y += w0 * h0.y + w1 * h1.y + w2 * h2.y + w3 * h3.y;
        acc.z += w0 * h0.z + w1 * h1.z + w2 * h2.z + w3 * h3.z;
        acc.w += w0 * h0.w + w1 * h1.w + w2 * h2.w + w3 * h3.w;
    }
    for (; i < e_; i++) {
        int r = g_srow[i];
        float w = g_dinv[r];
        float4 h = *(const float4*)(H + r * HID + d);
        acc.x += w * h.x; acc.y += w * h.y; acc.z += w * h.z; acc.w += w * h.w;
    }

    float4 b = *(const float4*)(bias + d);
    float4 v;
    v.x = fmaxf(b.x + dc * acc.x, 0.0f);
    v.y = fmaxf(b.y + dc * acc.y, 0.0f);
    v.z = fmaxf(b.z + dc * acc.z, 0.0f);
    v.w = fmaxf(b.w + dc * acc.w, 0.0f);
    *(float4*)(out + c * HID + d) = v;
}

// ---------------- software-pipelined SGEMM task ----------------
template <int BM, int BN, bool TRANSB, bool HAS_BIAS, bool DO_ADD, bool DO_RELU>
__device__ void pgemm_task(char* smraw,
                           const float* A, const float* B,
                           const float* bias, const float* add, float* C,
                           int M, int N, int K, int bx, int by) {
    constexpr int NA = BM / 32;
    constexpr int NB = BN / 32;
    constexpr int RM = BM / 16;
    constexpr int RN = BN / 16;
    typedef float AsRow[32][BM + 4];
    typedef float BsRow[32][BN];
    AsRow* As = reinterpret_cast<AsRow*>(smraw);
    BsRow* Bs = reinterpret_cast<BsRow*>(smraw + 2 * 32 * (BM + 4) * sizeof(float));

    const int tid = threadIdx.x;
    const int tx = tid & 15, ty = tid >> 4;
    const int m0 = by * BM, n0 = bx * BN;

    float4 pa[NA], pb[NB];

    auto loadA = [&](int k0) {
        #pragma unroll
        for (int i = 0; i < NA; i++) {
            int fl = tid + i * 256;
            int ar = fl >> 3, ac = (fl & 7) * 4;
            pa[i] = *(const float4*)(A + (m0 + ar) * K + k0 + ac);
        }
    };
    auto storeA = [&](int buf) {
        #pragma unroll
        for (int i = 0; i < NA; i++) {
            int fl = tid + i * 256;
            int ar = fl >> 3, ac = (fl & 7) * 4;
            As[buf][ac + 0][ar] = pa[i].x;
            As[buf][ac + 1][ar] = pa[i].y;
            As[buf][ac + 2][ar] = pa[i].z;
            As[buf][ac + 3][ar] = pa[i].w;
        }
    };
    auto loadB = [&](int k0) {
        #pragma unroll
        for (int i = 0; i < NB; i++) {
            int fl = tid + i * 256;
            if (!TRANSB) {
                int br = fl / (BN / 4), bc = (fl % (BN / 4)) * 4;
                pb[i] = *(const float4*)(B + (k0 + br) * N + n0 + bc);
            } else {
                int bn = fl >> 3, bk = (fl & 7) * 4;
                pb[i] = *(const float4*)(B + (n0 + bn) * K + k0 + bk);
            }
        }
    };
    auto storeB = [&](int buf) {
        #pragma unroll
        for (int i = 0; i < NB; i++) {
            int fl = tid + i * 256;
            if (!TRANSB) {
                int br = fl / (BN / 4), bc = (fl % (BN / 4)) * 4;
                *(float4*)&Bs[buf][br][bc] = pb[i];
            } else {
                int bn = fl >> 3, bk = (fl & 7) * 4;
                Bs[buf][bk + 0][bn] = pb[i].x;
                Bs[buf][bk + 1][bn] = pb[i].y;
                Bs[buf][bk + 2][bn] = pb[i].z;
                Bs[buf][bk + 3][bn] = pb[i].w;
            }
        }
    };

    loadA(0); loadB(0);
    storeA(0); storeB(0);
    __syncthreads();

    float acc[RM][RN];
    #pragma unroll
    for (int i = 0; i < RM; i++)
        #pragma unroll
        for (int j = 0; j < RN; j++) acc[i][j] = 0.0f;

    const int nit = K >> 5;
    for (int it = 0; it < nit; it++) {
        const int cur = it & 1;
        if (it + 1 < nit) { loadA((it + 1) * 32); loadB((it + 1) * 32); }

        #pragma unroll
        for (int kk = 0; kk < 32; kk++) {
            float a[RM], b[RN];
            if (RM == 4) {
                float4 av = *(const float4*)&As[cur][kk][ty * 4];
                a[0] = av.x; a[1] = av.y; a[2] = av.z; a[3] = av.w;
            } else {
                float2 av = *(const float2*)&As[cur][kk][ty * 2];
                a[0] = av.x; a[1] = av.y;
            }
            if (RN == 4) {
                float4 bv = *(const float4*)&Bs[cur][kk][tx * 4];
                b[0] = bv.x; b[1] = bv.y; b[2] = bv.z; b[3] = bv.w;
            } else {
                float2 bv = *(const float2*)&Bs[cur][kk][tx * 2];
                b[0] = bv.x; b[1] = bv.y;
            }
            #pragma unroll
            for (int i = 0; i < RM; i++)
                #pragma unroll
                for (int j = 0; j < RN; j++)
                    acc[i][j] += a[i] * b[j];
        }

        if (it + 1 < nit) {
            storeA((it + 1) & 1); storeB((it + 1) & 1);
            __syncthreads();
        }
    }

    #pragma unroll
    for (int i = 0; i < RM; i++) {
        int r = m0 + ty * RM + i;
        #pragma unroll
        for (int j = 0; j < RN; j++) {
            int c = n0 + tx * RN + j;
            float v = acc[i][j];
            if (HAS_BIAS) v += bias[c];
            if (DO_ADD)  v += add[r * N + c];
            if (DO_RELU) v = fmaxf(v, 0.0f);
            C[r * N + c] = v;
        }
    }
}

// ---------------- tensor-core flash attention task ----------------
__device__ __forceinline__ unsigned cvt_tf32(float f) {
    unsigned u; asm("cvt.rna.tf32.f32 %0, %1;" : "=r"(u) : "f"(f)); return u;
}
__device__ __forceinline__ unsigned f16x2_hl(float hi, float lo) {
    unsigned u; asm("cvt.rn.f16x2.f32 %0, %1, %2;" : "=r"(u) : "f"(hi), "f"(lo)); return u;
}
__device__ __forceinline__ float ex2(float x) {
    float y; asm("ex2.approx.ftz.f32 %0, %1;" : "=f"(y) : "f"(x)); return y;
}
__device__ __forceinline__ void mma_tf32(float c[4], const unsigned a[4],
                                         unsigned b0, unsigned b1) {
    asm("mma.sync.aligned.m16n8k8.row.col.f32.tf32.tf32.f32 "
        "{%0,%1,%2,%3}, {%4,%5,%6,%7}, {%8,%9}, {%0,%1,%2,%3};"
        : "+f"(c[0]), "+f"(c[1]), "+f"(c[2]), "+f"(c[3])
        : "r"(a[0]), "r"(a[1]), "r"(a[2]), "r"(a[3]), "r"(b0), "r"(b1));
}
__device__ __forceinline__ void mma_f16(float c[4], unsigned a0, unsigned a1,
                                        unsigned a2, unsigned a3,
                                        unsigned b0, unsigned b1) {
    asm("mma.sync.aligned.m16n8k16.row.col.f32.f16.f16.f32 "
        "{%0,%1,%2,%3}, {%4,%5,%6,%7}, {%8,%9}, {%0,%1,%2,%3};"
        : "+f"(c[0]), "+f"(c[1]), "+f"(c[2]), "+f"(c[3])
        : "r"(a0), "r"(a1), "r"(a2), "r"(a3), "r"(b0), "r"(b1));
}

__device__ void attn_task(char* smraw, const float* QKV, float* O, int task) {
    unsigned (*Ks)[17] = reinterpret_cast<unsigned(*)[17]>(smraw);
    float    (*Vs)[17] = reinterpret_cast<float(*)[17]>(smraw + 64 * 17 * 4);

    const int h    = task >> 5;
    const int qt   = task & 31;
    const int warp = threadIdx.x >> 5;
    const int lane = threadIdx.x & 31;
    const int g    = lane >> 2;
    const int t    = lane & 3;
    const int q0   = qt * 128 + warp * 16;

    const float qscale = 0.25f * 1.4426950408889634f;

    unsigned qa[2][4];
    {
        const float* Qb = QKV + h * HDIM;
        #pragma unroll
        for (int kk = 0; kk < 2; kk++) {
            qa[kk][0] = cvt_tf32(Qb[(q0 + g)     * 384 + kk * 8 + t]     * qscale);
            qa[kk][1] = cvt_tf32(Qb[(q0 + g + 8) * 384 + kk * 8 + t]     * qscale);
            qa[kk][2] = cvt_tf32(Qb[(q0 + g)     * 384 + kk * 8 + t + 4] * qscale);
            qa[kk][3] = cvt_tf32(Qb[(q0 + g + 8) * 384 + kk * 8 + t + 4] * qscale);
        }
    }

    float o[2][4];
    #pragma unroll
    for (int dt = 0; dt < 2; dt++)
        #pragma unroll
        for (int i = 0; i < 4; i++) o[dt][i] = 0.0f;
    float l0 = 0.0f, l1 = 0.0f;

    for (int k0 = 0; k0 < NN; k0 += 64) {
        __syncthreads();
        {
            int key = threadIdx.x & 63;
            int dh  = (threadIdx.x >> 6) * 4;
            const float* kb = QKV + (k0 + key) * 384 + FF + h * HDIM + dh;
            float4 kv = *(const float4*)kb;
            float4 vv = *(const float4*)(kb + FF);
            Ks[key][dh + 0] = cvt_tf32(kv.x);
            Ks[key][dh + 1] = cvt_tf32(kv.y);
            Ks[key][dh + 2] = cvt_tf32(kv.z);
            Ks[key][dh + 3] = cvt_tf32(kv.w);
            Vs[key][dh + 0] = vv.x;
            Vs[key][dh + 1] = vv.y;
            Vs[key][dh + 2] = vv.z;
            Vs[key][dh + 3] = vv.w;
        }
        __syncthreads();

        float c[8][4];
        #pragma unroll
        for (int j = 0; j < 8; j++) {
            c[j][0] = c[j][1] = c[j][2] = c[j][3] = 0.0f;
            #pragma unroll
            for (int kk = 0; kk < 2; kk++) {
                unsigned b0 = Ks[j * 8 + g][kk * 8 + t];
                unsigned b1 = Ks[j * 8 + g][kk * 8 + t + 4];
                mma_tf32(c[j], qa[kk], b0, b1);
            }
        }

        #pragma unroll
        for (int j = 0; j < 8; j++) {
            c[j][0] = ex2(c[j][0] - 8.0f);
            c[j][1] = ex2(c[j][1] - 8.0f);
            c[j][2] = ex2(c[j][2] - 8.0f);
            c[j][3] = ex2(c[j][3] - 8.0f);
            l0 += c[j][0] + c[j][1];
            l1 += c[j][2] + c[j][3];
        }

        #pragma unroll
        for (int kt = 0; kt < 4; kt++) {
            unsigned a0 = f16x2_hl(c[2 * kt][1],     c[2 * kt][0]);
            unsigned a1 = f16x2_hl(c[2 * kt][3],     c[2 * kt][2]);
            unsigned a2 = f16x2_hl(c[2 * kt + 1][1], c[2 * kt + 1][0]);
            unsigned a3 = f16x2_hl(c[2 * kt + 1][3], c[2 * kt + 1][2]);
            int kb = kt * 16;
            #pragma unroll
            for (int dt = 0; dt < 2; dt++) {
                int d = dt * 8 + g;
                unsigned b0 = f16x2_hl(Vs[kb + 2 * t + 1][d], Vs[kb + 2 * t][d]);
                unsigned b1 = f16x2_hl(Vs[kb + 2 * t + 9][d], Vs[kb + 2 * t + 8][d]);
                mma_f16(o[dt], a0, a1, a2, a3, b0, b1);
            }
        }
    }

    l0 += __shfl_xor_sync(0xffffffffu, l0, 1);
    l0 += __shfl_xor_sync(0xffffffffu, l0, 2);
    l1 += __shfl_xor_sync(0xffffffffu, l1, 1);
    l1 += __shfl_xor_sync(0xffffffffu, l1, 2);
    float inv0 = 1.0f / l0;
    float inv1 = 1.0f / l1;

    #pragma unroll
    for (int dt = 0; dt < 2; dt++) {
        int col = h * HDIM + dt * 8 + 2 * t;
        float2 v0 = make_float2(o[dt][0] * inv0, o[dt][1] * inv0);
        float2 v1 = make_float2(o[dt][2] * inv1, o[dt][3] * inv1);
        *(float2*)(O + (q0 + g)     * FF + col) = v0;
        *(float2*)(O + (q0 + g + 8) * FF + col) = v1;
    }
}

// ---------------- the megakernel ----------------
__global__ __launch_bounds__(NT, 2)
void mega_kernel(const float* __restrict__ x, const int* __restrict__ edge_index,
                 const float* __restrict__ W1, const float* __restrict__ b1,
                 const float* __restrict__ W2, const float* __restrict__ b2,
                 const float* __restrict__ W3, const float* __restrict__ b3,
                 const float* __restrict__ in_w, const float* __restrict__ in_b,
                 const float* __restrict__ out_w, const float* __restrict__ out_b,
                 const float* __restrict__ proj_w, const float* __restrict__ proj_b,
                 float* __restrict__ out) {
    // max smem user: pgemm<64,64>: 2*32*68*4 + 2*32*64*4 = 17408 + 16384 = 33792 B
    __shared__ __align__(16) char smraw[33792];

    const int* row = edge_index;
    const int* col = edge_index + EE;

    // P0: Wp precompute (32) + degree histogram (128)
    run_phase(0, 32 + 128, [&](int t) {
        if (t < 32) wp_task(out_w, out_b, proj_w, proj_b, t);
        else        hist_task(col, t - 32);
    });
    grid_barrier(0);

    // P1: scan (1) + QKV GEMM (384) + conv1 GEMM (256)
    run_phase(1, 1 + 384 + 256, [&](int t) {
        if (t == 0)       scan_task(smraw);
        else if (t <= 384) {
            int tt = t - 1;
            pgemm_task<64, 64, true, true, false, false>(
                smraw, x, in_w, in_b, nullptr, g_QKV, NN, 3 * FF, FF, tt % 6, tt / 6);
        } else {
            int tt = t - 385;
            pgemm_task<64, 32, false, false, false, false>(
                smraw, x, W1, nullptr, nullptr, g_H, NN, HID, FF, tt % 4, tt / 4);
        }
    });
    grid_barrier(1);

    // P2: attention (256) + reorder (64)
    run_phase(2, 256 + 64, [&](int t) {
        if (t < 256) attn_task(smraw, g_QKV, g_O, t);
        else         reorder_task(row, col, t - 256);
    });
    grid_barrier(2);

    // P3: gather1 (512)
    run_phase(3, 512, [&](int t) { gather_task(g_H, b1, g_G, t); });
    grid_barrier(3);

    // P4: conv2 GEMM (256)
    run_phase(4, 256, [&](int t) {
        pgemm_task<64, 32, false, false, false, false>(
            smraw, g_G, W2, nullptr, nullptr, g_H, NN, HID, HID, t % 4, t / 4);
    });
    grid_barrier(4);

    // P5: gather2 (512)
    run_phase(5, 512, [&](int t) { gather_task(g_H, b2, g_G2, t); });
    grid_barrier(5);

    // P6: GNN head GEMM (256)
    run_phase(6, 256, [&](int t) {
        pgemm_task<32, 32, false, true, false, false>(
            smraw, g_G2, W3, b3, nullptr, g_GNN, NN, CC, HID, t % 2, t / 2);
    });
    grid_barrier(6);

    // P7: final fused GEMM: out = relu(O @ Wp + bp + GNN)
    run_phase(7, 256, [&](int t) {
        pgemm_task<32, 32, false, true, true, true>(
            smraw, g_O, g_Wp, g_bp, g_GNN, out, NN, CC, FF, t % 2, t / 2);
    });
    grid_barrier(7);   // also resets ticket[7] for the next launch
}

// ---------------- launch ----------------
extern "C" void kernel_launch(void* const* d_in, const int* in_sizes, int n_in,
                              void* d_out, int out_size) {
    const float* x          = (const float*)d_in[0];
    const int*   edge_index = (const int*)  d_in[1];
    const float* W1         = (const float*)d_in[2];
    const float* b1         = (const float*)d_in[3];
    const float* W2         = (const float*)d_in[4];
    const float* b2         = (const float*)d_in[5];
    const float* W3         = (const float*)d_in[6];
    const float* b3         = (const float*)d_in[7];
    const float* in_w       = (const float*)d_in[8];
    const float* in_b       = (const float*)d_in[9];
    const float* out_w      = (const float*)d_in[10];
    const float* out_b      = (const float*)d_in[11];
    const float* proj_w     = (const float*)d_in[12];
    const float* proj_b     = (const float*)d_in[13];
    float* out = (float*)d_out;

    mega_kernel<<<GRID, NT>>>(x, edge_index, W1, b1, W2, b2, W3, b3,
                              in_w, in_b, out_w, out_b, proj_w, proj_b, out);
}

// round 14
// speedup vs baseline: 1.8837x; 1.4743x over previous
#include <cuda_runtime.h>
#include <cuda_fp16.h>
#include <cstdint>

// Problem constants
#define NN 4096
#define FF 128
#define HID 128
#define HEADS 8
#define HDIM 16
#define CC 64
#define EE 131072

// ---------------- scratch (no allocation allowed) ----------------
__device__ float g_H[NN * HID];     // GEMM output of X@W (pre-gather)
__device__ float g_G[NN * HID];     // conv1 output (post-relu)
__device__ float g_G2[NN * HID];    // conv2 output (post-relu)
__device__ float g_QKV[NN * 3 * FF];
__device__ float g_O[NN * FF];      // attention output
__device__ float g_GNN[NN * CC];    // gnn branch output
__device__ float g_Wp[FF * CC];     // fused out_proj*proj weight
__device__ float g_bp[CC];          // fused bias
__device__ float g_dinv[NN];
__device__ int   g_count[NN];
__device__ int   g_off[NN + 1];
__device__ int   g_cur[NN];
__device__ int   g_srow[EE];

// ---------------- helpers ----------------
__device__ __forceinline__ unsigned f16x2_hl(float hi, float lo) {
    unsigned u; asm("cvt.rn.f16x2.f32 %0, %1, %2;" : "=r"(u) : "f"(hi), "f"(lo)); return u;
}
__device__ __forceinline__ float ex2(float x) {
    float y; asm("ex2.approx.ftz.f32 %0, %1;" : "=f"(y) : "f"(x)); return y;
}
__device__ __forceinline__ void mma_f16(float c[4], unsigned a0, unsigned a1,
                                        unsigned a2, unsigned a3,
                                        unsigned b0, unsigned b1) {
    asm("mma.sync.aligned.m16n8k16.row.col.f32.f16.f16.f32 "
        "{%0,%1,%2,%3}, {%4,%5,%6,%7}, {%8,%9}, {%0,%1,%2,%3};"
        : "+f"(c[0]), "+f"(c[1]), "+f"(c[2]), "+f"(c[3])
        : "r"(a0), "r"(a1), "r"(a2), "r"(a3), "r"(b0), "r"(b1));
}

// ---------------- CSR build kernels (round-6) ----------------
__global__ void zero_count_kernel(int* count) {
    int i = blockIdx.x * blockDim.x + threadIdx.x;
    if (i < NN) count[i] = 0;
}

__global__ void hist_kernel(const int* __restrict__ col, int* __restrict__ count) {
    int e = blockIdx.x * blockDim.x + threadIdx.x;
    if (e < EE) atomicAdd(&count[col[e]], 1);
}

__global__ __launch_bounds__(1024)
void scan_kernel(const int* __restrict__ count, int* __restrict__ off,
                 int* __restrict__ cur, float* __restrict__ dinv) {
    __shared__ int wsum[32];
    int t = threadIdx.x;
    int lane = t & 31, warp = t >> 5;
    int base = t * 4;
    int v0 = count[base + 0], v1 = count[base + 1];
    int v2 = count[base + 2], v3 = count[base + 3];
    dinv[base + 0] = rsqrtf(1.0f + (float)v0);
    dinv[base + 1] = rsqrtf(1.0f + (float)v1);
    dinv[base + 2] = rsqrtf(1.0f + (float)v2);
    dinv[base + 3] = rsqrtf(1.0f + (float)v3);
    int s = v0 + v1 + v2 + v3;
    int x = s;
    #pragma unroll
    for (int d = 1; d < 32; d <<= 1) {
        int y = __shfl_up_sync(0xffffffffu, x, d);
        if (lane >= d) x += y;
    }
    if (lane == 31) wsum[warp] = x;
    __syncthreads();
    if (warp == 0) {
        int w = wsum[lane];
        #pragma unroll
        for (int d = 1; d < 32; d <<= 1) {
            int y = __shfl_up_sync(0xffffffffu, w, d);
            if (lane >= d) w += y;
        }
        wsum[lane] = w;
    }
    __syncthreads();
    int run = x - s + (warp ? wsum[warp - 1] : 0);
    off[base + 0] = run; cur[base + 0] = run; run += v0;
    off[base + 1] = run; cur[base + 1] = run; run += v1;
    off[base + 2] = run; cur[base + 2] = run; run += v2;
    off[base + 3] = run; cur[base + 3] = run; run += v3;
    if (t == 1023) off[NN] = run;
}

__global__ void reorder_kernel(const int* __restrict__ row, const int* __restrict__ col,
                               int* __restrict__ cur, int* __restrict__ srow) {
    int e = blockIdx.x * blockDim.x + threadIdx.x;
    if (e >= EE) return;
    int pos = atomicAdd(&cur[col[e]], 1);
    srow[pos] = row[e];
}

// ---------------- fused projection weight (round-7, verified) --------------
__global__ __launch_bounds__(256)
void wp_kernel(const float* __restrict__ out_w, const float* __restrict__ out_b,
               const float* __restrict__ proj_w, const float* __restrict__ proj_b,
               float* __restrict__ Wp, float* __restrict__ bp) {
    int gid = blockIdx.x * 256 + threadIdx.x;   // 8192 threads
    int i = gid >> 6;
    int c = gid & 63;
    float acc = 0.0f;
    #pragma unroll 8
    for (int o = 0; o < FF; o++)
        acc += out_w[o * FF + i] * proj_w[o * CC + c];
    Wp[i * CC + c] = acc;
    if (i == 0) {
        float b = proj_b[c];
        #pragma unroll 8
        for (int o = 0; o < FF; o++)
            b += out_b[o] * proj_w[o * CC + c];
        bp[c] = b;
    }
}

// ---------------- segmented gather (round-6) ----------------
__global__ __launch_bounds__(256)
void gather_kernel(const float* __restrict__ H,
                   const int* __restrict__ srow, const int* __restrict__ off,
                   const float* __restrict__ dinv, const float* __restrict__ bias,
                   float* __restrict__ out) {
    int warp = threadIdx.x >> 5;
    int lane = threadIdx.x & 31;
    int c = blockIdx.x * 8 + warp;
    int d = lane * 4;

    float dc = dinv[c];
    float4 hs = *(const float4*)(H + c * HID + d);
    float4 acc = make_float4(dc * hs.x, dc * hs.y, dc * hs.z, dc * hs.w);

    int i = off[c];
    int e_ = off[c + 1];
    for (; i + 4 <= e_; i += 4) {
        int r0 = srow[i], r1 = srow[i + 1], r2 = srow[i + 2], r3 = srow[i + 3];
        float w0 = dinv[r0], w1 = dinv[r1], w2 = dinv[r2], w3 = dinv[r3];
        float4 h0 = *(const float4*)(H + r0 * HID + d);
        float4 h1 = *(const float4*)(H + r1 * HID + d);
        float4 h2 = *(const float4*)(H + r2 * HID + d);
        float4 h3 = *(const float4*)(H + r3 * HID + d);
        acc.x += w0 * h0.x + w1 * h1.x + w2 * h2.x + w3 * h3.x;
        acc.y += w0 * h0.y + w1 * h1.y + w2 * h2.y + w3 * h3.y;
        acc.z += w0 * h0.z + w1 * h1.z + w2 * h2.z + w3 * h3.z;
        acc.w += w0 * h0.w + w1 * h1.w + w2 * h2.w + w3 * h3.w;
    }
    for (; i < e_; i++) {
        int r = srow[i];
        float w = dinv[r];
        float4 h = *(const float4*)(H + r * HID + d);
        acc.x += w * h.x; acc.y += w * h.y; acc.z += w * h.z; acc.w += w * h.w;
    }

    float4 b = *(const float4*)(bias + d);
    float4 v;
    v.x = fmaxf(b.x + dc * acc.x, 0.0f);
    v.y = fmaxf(b.y + dc * acc.y, 0.0f);
    v.z = fmaxf(b.z + dc * acc.z, 0.0f);
    v.w = fmaxf(b.w + dc * acc.w, 0.0f);
    *(float4*)(out + c * HID + d) = v;
}

// ---------------- software-pipelined SGEMM (round-6) ----------------
template <int BM, int BN, bool TRANSB, bool HAS_BIAS, bool DO_ADD, bool DO_RELU>
__global__ __launch_bounds__(256)
void pgemm_kernel(const float* __restrict__ A, const float* __restrict__ B,
                  const float* __restrict__ bias, const float* __restrict__ add,
                  float* __restrict__ C, int M, int N, int K) {
    constexpr int NA = BM / 32;
    constexpr int NB = BN / 32;
    constexpr int RM = BM / 16;
    constexpr int RN = BN / 16;
    __shared__ float As[2][32][BM + 4];
    __shared__ float Bs[2][32][BN];

    const int tid = threadIdx.x;
    const int tx = tid & 15, ty = tid >> 4;
    const int m0 = blockIdx.y * BM, n0 = blockIdx.x * BN;

    float4 pa[NA], pb[NB];

    auto loadA = [&](int k0) {
        #pragma unroll
        for (int i = 0; i < NA; i++) {
            int fl = tid + i * 256;
            int ar = fl >> 3, ac = (fl & 7) * 4;
            pa[i] = *(const float4*)(A + (m0 + ar) * K + k0 + ac);
        }
    };
    auto storeA = [&](int buf) {
        #pragma unroll
        for (int i = 0; i < NA; i++) {
            int fl = tid + i * 256;
            int ar = fl >> 3, ac = (fl & 7) * 4;
            As[buf][ac + 0][ar] = pa[i].x;
            As[buf][ac + 1][ar] = pa[i].y;
            As[buf][ac + 2][ar] = pa[i].z;
            As[buf][ac + 3][ar] = pa[i].w;
        }
    };
    auto loadB = [&](int k0) {
        #pragma unroll
        for (int i = 0; i < NB; i++) {
            int fl = tid + i * 256;
            if (!TRANSB) {
                int br = fl / (BN / 4), bc = (fl % (BN / 4)) * 4;
                pb[i] = *(const float4*)(B + (k0 + br) * N + n0 + bc);
            } else {
                int bn = fl >> 3, bk = (fl & 7) * 4;
                pb[i] = *(const float4*)(B + (n0 + bn) * K + k0 + bk);
            }
        }
    };
    auto storeB = [&](int buf) {
        #pragma unroll
        for (int i = 0; i < NB; i++) {
            int fl = tid + i * 256;
            if (!TRANSB) {
                int br = fl / (BN / 4), bc = (fl % (BN / 4)) * 4;
                *(float4*)&Bs[buf][br][bc] = pb[i];
            } else {
                int bn = fl >> 3, bk = (fl & 7) * 4;
                Bs[buf][bk + 0][bn] = pb[i].x;
                Bs[buf][bk + 1][bn] = pb[i].y;
                Bs[buf][bk + 2][bn] = pb[i].z;
                Bs[buf][bk + 3][bn] = pb[i].w;
            }
        }
    };

    loadA(0); loadB(0);
    storeA(0); storeB(0);
    __syncthreads();

    float acc[RM][RN];
    #pragma unroll
    for (int i = 0; i < RM; i++)
        #pragma unroll
        for (int j = 0; j < RN; j++) acc[i][j] = 0.0f;

    const int nit = K >> 5;
    for (int it = 0; it < nit; it++) {
        const int cur = it & 1;
        if (it + 1 < nit) { loadA((it + 1) * 32); loadB((it + 1) * 32); }

        #pragma unroll
        for (int kk = 0; kk < 32; kk++) {
            float a[RM], b[RN];
            if (RM == 4) {
                float4 av = *(const float4*)&As[cur][kk][ty * 4];
                a[0] = av.x; a[1] = av.y; a[2] = av.z; a[3] = av.w;
            } else {
                float2 av = *(const float2*)&As[cur][kk][ty * 2];
                a[0] = av.x; a[1] = av.y;
            }
            if (RN == 4) {
                float4 bv = *(const float4*)&Bs[cur][kk][tx * 4];
                b[0] = bv.x; b[1] = bv.y; b[2] = bv.z; b[3] = bv.w;
            } else {
                float2 bv = *(const float2*)&Bs[cur][kk][tx * 2];
                b[0] = bv.x; b[1] = bv.y;
            }
            #pragma unroll
            for (int i = 0; i < RM; i++)
                #pragma unroll
                for (int j = 0; j < RN; j++)
                    acc[i][j] += a[i] * b[j];
        }

        if (it + 1 < nit) {
            storeA((it + 1) & 1); storeB((it + 1) & 1);
            __syncthreads();
        }
    }

    #pragma unroll
    for (int i = 0; i < RM; i++) {
        int r = m0 + ty * RM + i;
        #pragma unroll
        for (int j = 0; j < RN; j++) {
            int c = n0 + tx * RN + j;
            float v = acc[i][j];
            if (HAS_BIAS) v += bias[c];
            if (DO_ADD)  v += add[r * N + c];
            if (DO_RELU) v = fmaxf(v, 0.0f);
            C[r * N + c] = v;
        }
    }
}

// ---------------- fp16 tensor-core flash attention ----------------
// S = Q K^T via m16n8k16.f16 (same 10-bit mantissa as tf32 -> accuracy-neutral).
// K stored in smem as packed f16x2 [key][dim/2] (stride 12 words: frag loads
// conflict-free, 1 LDS per B-reg). V stored TRANSPOSED fp16 [dim][key]
// (stride 72 halves: frag loads conflict-free, 1 LDS per B-reg).
__global__ __launch_bounds__(256)
void attn_f16_kernel(const float* __restrict__ QKV, float* __restrict__ O) {
    const int h    = blockIdx.y;
    const int warp = threadIdx.x >> 5;
    const int lane = threadIdx.x & 31;
    const int g    = lane >> 2;
    const int t    = lane & 3;
    const int q0   = blockIdx.x * 128 + warp * 16;

    __shared__ unsigned Kw[64 * 12];   // f16x2 K: [key][dim pair], 3 KB
    __shared__ __half   Vt[16][72];    // fp16 V^T: [dim][key], 2.25 KB

    const float qscale = 0.25f * 1.4426950408889634f;  // (1/sqrt(hd)) * log2(e)

    // Q a-fragments for full k=16 (fp16x2 pairs of consecutive dims)
    unsigned qa0, qa1, qa2, qa3;
    {
        const float* r0 = QKV + (q0 + g)     * 384 + h * HDIM;
        const float* r1 = QKV + (q0 + g + 8) * 384 + h * HDIM;
        qa0 = f16x2_hl(r0[2 * t + 1] * qscale, r0[2 * t]     * qscale);
        qa1 = f16x2_hl(r1[2 * t + 1] * qscale, r1[2 * t]     * qscale);
        qa2 = f16x2_hl(r0[2 * t + 9] * qscale, r0[2 * t + 8] * qscale);
        qa3 = f16x2_hl(r1[2 * t + 9] * qscale, r1[2 * t + 8] * qscale);
    }

    float o[2][4];
    #pragma unroll
    for (int dt = 0; dt < 2; dt++)
        #pragma unroll
        for (int i = 0; i < 4; i++) o[dt][i] = 0.0f;
    float l0 = 0.0f, l1 = 0.0f;

    const unsigned* Vtw = (const unsigned*)&Vt[0][0];

    for (int k0 = 0; k0 < NN; k0 += 64) {
        __syncthreads();
        {
            int key = threadIdx.x & 63;
            int dh  = (threadIdx.x >> 6) * 4;
            const float* kb = QKV + (k0 + key) * 384 + FF + h * HDIM + dh;
            float4 kv = *(const float4*)kb;
            float4 vv = *(const float4*)(kb + FF);
            Kw[key * 12 + (dh >> 1) + 0] = f16x2_hl(kv.y, kv.x);
            Kw[key * 12 + (dh >> 1) + 1] = f16x2_hl(kv.w, kv.z);
            Vt[dh + 0][key] = __float2half_rn(vv.x);
            Vt[dh + 1][key] = __float2half_rn(vv.y);
            Vt[dh + 2][key] = __float2half_rn(vv.z);
            Vt[dh + 3][key] = __float2half_rn(vv.w);
        }
        __syncthreads();

        // S = Q K^T : 8 n-tiles of 8 keys, one k16 mma each
        float c[8][4];
        #pragma unroll
        for (int j = 0; j < 8; j++) {
            c[j][0] = c[j][1] = c[j][2] = c[j][3] = 0.0f;
            unsigned b0 = Kw[(j * 8 + g) * 12 + t];       // dims 2t,2t+1
            unsigned b1 = Kw[(j * 8 + g) * 12 + t + 4];   // dims 2t+8,2t+9
            mma_f16(c[j], qa0, qa1, qa2, qa3, b0, b1);
        }

        // p = exp2(s - 8), accumulate row sums
        #pragma unroll
        for (int j = 0; j < 8; j++) {
            c[j][0] = ex2(c[j][0] - 8.0f);
            c[j][1] = ex2(c[j][1] - 8.0f);
            c[j][2] = ex2(c[j][2] - 8.0f);
            c[j][3] = ex2(c[j][3] - 8.0f);
            l0 += c[j][0] + c[j][1];
            l1 += c[j][2] + c[j][3];
        }

        // O += P V : B-fragments are single 32-bit loads from transposed V
        #pragma unroll
        for (int kt = 0; kt < 4; kt++) {
            unsigned a0 = f16x2_hl(c[2 * kt][1],     c[2 * kt][0]);
            unsigned a1 = f16x2_hl(c[2 * kt][3],     c[2 * kt][2]);
            unsigned a2 = f16x2_hl(c[2 * kt + 1][1], c[2 * kt + 1][0]);
            unsigned a3 = f16x2_hl(c[2 * kt + 1][3], c[2 * kt + 1][2]);
            #pragma unroll
            for (int dt = 0; dt < 2; dt++) {
                int d = dt * 8 + g;
                unsigned b0 = Vtw[d * 36 + kt * 8 + t];       // keys kt*16+2t, +2t+1
                unsigned b1 = Vtw[d * 36 + kt * 8 + t + 4];   // keys kt*16+8+2t, ...
                mma_f16(o[dt], a0, a1, a2, a3, b0, b1);
            }
        }
    }

    l0 += __shfl_xor_sync(0xffffffffu, l0, 1);
    l0 += __shfl_xor_sync(0xffffffffu, l0, 2);
    l1 += __shfl_xor_sync(0xffffffffu, l1, 1);
    l1 += __shfl_xor_sync(0xffffffffu, l1, 2);
    float inv0 = 1.0f / l0;
    float inv1 = 1.0f / l1;

    #pragma unroll
    for (int dt = 0; dt < 2; dt++) {
        int col = h * HDIM + dt * 8 + 2 * t;
        float2 v0 = make_float2(o[dt][0] * inv0, o[dt][1] * inv0);
        float2 v1 = make_float2(o[dt][2] * inv1, o[dt][3] * inv1);
        *(float2*)(O + (q0 + g)     * FF + col) = v0;
        *(float2*)(O + (q0 + g + 8) * FF + col) = v1;
    }
}

// ---------------- launch ----------------
extern "C" void kernel_launch(void* const* d_in, const int* in_sizes, int n_in,
                              void* d_out, int out_size) {
    const float* x          = (const float*)d_in[0];
    const int*   edge_index = (const int*)  d_in[1];
    const float* W1         = (const float*)d_in[2];
    const float* b1         = (const float*)d_in[3];
    const float* W2         = (const float*)d_in[4];
    const float* b2         = (const float*)d_in[5];
    const float* W3         = (const float*)d_in[6];
    const float* b3         = (const float*)d_in[7];
    const float* in_w       = (const float*)d_in[8];
    const float* in_b       = (const float*)d_in[9];
    const float* out_w      = (const float*)d_in[10];
    const float* out_b      = (const float*)d_in[11];
    const float* proj_w     = (const float*)d_in[12];
    const float* proj_b     = (const float*)d_in[13];
    float* out = (float*)d_out;

    const int* row = edge_index;
    const int* col = edge_index + EE;

    float *H, *G, *G2, *QKV, *O, *GNN, *Wp, *bp, *dinv;
    int *cnt, *off, *cur, *srow;
    cudaGetSymbolAddress((void**)&H,    g_H);
    cudaGetSymbolAddress((void**)&G,    g_G);
    cudaGetSymbolAddress((void**)&G2,   g_G2);
    cudaGetSymbolAddress((void**)&QKV,  g_QKV);
    cudaGetSymbolAddress((void**)&O,    g_O);
    cudaGetSymbolAddress((void**)&GNN,  g_GNN);
    cudaGetSymbolAddress((void**)&Wp,   g_Wp);
    cudaGetSymbolAddress((void**)&bp,   g_bp);
    cudaGetSymbolAddress((void**)&dinv, g_dinv);
    cudaGetSymbolAddress((void**)&cnt,  g_count);
    cudaGetSymbolAddress((void**)&off,  g_off);
    cudaGetSymbolAddress((void**)&cur,  g_cur);
    cudaGetSymbolAddress((void**)&srow, g_srow);

    // ---- CSR build ----
    zero_count_kernel<<<(NN + 255) / 256, 256>>>(cnt);
    hist_kernel<<<(EE + 255) / 256, 256>>>(col, cnt);
    scan_kernel<<<1, 1024>>>(cnt, off, cur, dinv);
    reorder_kernel<<<(EE + 255) / 256, 256>>>(row, col, cur, srow);

    // ---- fused projection weight (independent of everything else) ----
    wp_kernel<<<FF * CC / 256, 256>>>(out_w, out_b, proj_w, proj_b, Wp, bp);

    // ---- GCN conv 1: H = x@W1 ; G = relu(gather) ----
    pgemm_kernel<64, 32, false, false, false, false>
        <<<dim3(HID / 32, NN / 64), 256>>>(x, W1, nullptr, nullptr, H, NN, HID, FF);
    gather_kernel<<<NN / 8, 256>>>(H, srow, off, dinv, b1, G);

    // ---- GCN conv 2: H = G@W2 ; G2 = relu(gather) ----
    pgemm_kernel<64, 32, false, false, false, false>
        <<<dim3(HID / 32, NN / 64), 256>>>(G, W2, nullptr, nullptr, H, NN, HID, HID);
    gather_kernel<<<NN / 8, 256>>>(H, srow, off, dinv, b2, G2);

    // ---- GNN head: GNN = G2 @ W3 + b3 ----
    pgemm_kernel<32, 32, false, true, false, false>
        <<<dim3(CC / 32, NN / 32), 256>>>(G2, W3, b3, nullptr, GNN, NN, CC, HID);

    // ---- Transformer branch ----
    pgemm_kernel<64, 64, true, true, false, false>
        <<<dim3(3 * FF / 64, NN / 64), 256>>>(x, in_w, in_b, nullptr, QKV, NN, 3 * FF, FF);
    attn_f16_kernel<<<dim3(NN / 128, HEADS), 256>>>(QKV, O);

    // ---- join: out = relu(O @ Wp + bp + GNN) ----
    pgemm_kernel<32, 32, false, true, true, true>
        <<<dim3(CC / 32, NN / 32), 256>>>(O, Wp, bp, GNN, out, NN, CC, FF);
}